// round 15
// baseline (speedup 1.0000x reference)
#include <cuda_runtime.h>
#include <cuda_fp16.h>
#include <cstdint>

#define T_STEPS 512
#define BATCH   64
#define IDIM    1024
#define HDIM    1024
#define G4      4096
#define KDIM    1024
#define NCTA2   256             // recur CTAs: (j 0..127) x (K-half s 0..1)
#define SLOTS2  4096            // uint2 fragment slots per recur CTA per array
#define ASTR    36              // recur A smem row stride (conflict-free LDSM)
#define XSTR    20              // xproj smem row stride

__device__ float g_Zx[(size_t)T_STEPS * BATCH * G4];
__device__ uint2 g_WfragH[(size_t)NCTA2 * SLOTS2];
__device__ uint2 g_WfragM[(size_t)NCTA2 * SLOTS2];
__device__ float g_Part[(size_t)128 * 2048];        // K-half-1 partial z tiles
__device__ unsigned g_flags[NCTA2 * 32];            // step barrier flags
__device__ unsigned g_pflags[128 * 32];             // partial-ready flags

// ---------------------------------------------------------------- helpers
__device__ __forceinline__ void split_pair(float e, float o, uint32_t& ph, uint32_t& pm) {
    __half2 hp = __floats2half2_rn(e, o);
    float2 hf = __half22float2(hp);
    __half2 mp = __floats2half2_rn(e - hf.x, o - hf.y);
    ph = *reinterpret_cast<uint32_t*>(&hp);
    pm = *reinterpret_cast<uint32_t*>(&mp);
}
__device__ __forceinline__ void mma16(float* c, const uint32_t* a, const uint32_t* b) {
    asm volatile(
        "mma.sync.aligned.m16n8k16.row.col.f32.f16.f16.f32 "
        "{%0,%1,%2,%3},{%4,%5,%6,%7},{%8,%9},{%0,%1,%2,%3};\n"
        : "+f"(c[0]), "+f"(c[1]), "+f"(c[2]), "+f"(c[3])
        : "r"(a[0]), "r"(a[1]), "r"(a[2]), "r"(a[3]), "r"(b[0]), "r"(b[1]));
}
__device__ __forceinline__ void mma16h(uint32_t* c, const uint32_t* a, const uint32_t* b) {
    asm volatile(
        "mma.sync.aligned.m16n8k16.row.col.f16.f16.f16.f16 "
        "{%0,%1},{%2,%3,%4,%5},{%6,%7},{%0,%1};\n"
        : "+r"(c[0]), "+r"(c[1])
        : "r"(a[0]), "r"(a[1]), "r"(a[2]), "r"(a[3]), "r"(b[0]), "r"(b[1]));
}
__device__ __forceinline__ void ldsm_x4(uint32_t* r, uint32_t saddr) {
    asm volatile("ldmatrix.sync.aligned.m8n8.x4.shared.b16 {%0,%1,%2,%3}, [%4];"
                 : "=r"(r[0]), "=r"(r[1]), "=r"(r[2]), "=r"(r[3]) : "r"(saddr));
}
__device__ __forceinline__ void merge_cross(float* acc, const uint32_t* cx) {
    float2 lo = __half22float2(*reinterpret_cast<const __half2*>(&cx[0]));
    float2 hi = __half22float2(*reinterpret_cast<const __half2*>(&cx[1]));
    acc[0] += lo.x; acc[1] += lo.y; acc[2] += hi.x; acc[3] += hi.y;
}
__device__ __forceinline__ float sigmf(float x) { return 1.0f / (1.0f + expf(-x)); }

// ====== wfrag: w_hh -> per-(j,s) fragment order; reset flags ================
__global__ void __launch_bounds__(256)
wfrag_kernel(const float* __restrict__ w_hh) {
    size_t s = (size_t)blockIdx.x * 256 + threadIdx.x;   // 0 .. 1M-1
    if (s < NCTA2) g_flags[s * 32] = 0u;
    if (s < 128)   g_pflags[s * 32] = 0u;
    int cta = (int)(s >> 12);            // 0..255
    int r = (int)(s & (SLOTS2 - 1));
    int lane = r & 31, q = r >> 5;       // q 0..127
    int nt = q & 1, wn = (q >> 1) & 1, kk = (q >> 2) & 3, c = q >> 4;  // c 0..7
    int g = lane >> 2, tg = lane & 3;
    int j = cta >> 1, sh = cta & 1;
    int row = wn * 16 + nt * 8 + g;
    size_t R = (size_t)((row >> 3) * HDIM + j * 8 + (row & 7));
    int p0 = sh * 256 + c * 32 + kk * 8 + tg;
    const float* wr = w_hh + R * KDIM;
    uint32_t h0w, m0w, h1w, m1w;
    split_pair(wr[2 * p0],     wr[2 * p0 + 1], h0w, m0w);
    split_pair(wr[2 * p0 + 8], wr[2 * p0 + 9], h1w, m1w);
    g_WfragH[s] = make_uint2(h0w, h1w);
    g_WfragM[s] = make_uint2(m0w, m1w);
}

// ============ Phase 1: Z_x = x @ w_ih^T + bias (R10-exact) =================
extern __shared__ uint32_t xsm_u[];
#define XA(arr, buf, row, col) xsm_u[((((arr) * 2 + (buf)) * 128 + (row)) * XSTR) + (col)]
__global__ void __launch_bounds__(256)
xproj_kernel(const float* __restrict__ x, const float* __restrict__ w_ih,
             const float* __restrict__ b_ih, const float* __restrict__ b_hh,
             const int* __restrict__ biasflag) {
    int tid = threadIdx.x, warp = tid >> 5, lane = tid & 31;
    int g = lane >> 2, tg = lane & 3;
    int wm = warp >> 2, wn = warp & 3;
    int m_base = blockIdx.y * 128, n_base = blockIdx.x * 128;

    int srow[4], sc4[4];
#pragma unroll
    for (int it = 0; it < 4; it++) {
        int i = tid + it * 256;
        srow[it] = i >> 3;
        sc4[it] = i & 7;
    }

    float acc[4][4][4] = {};
    uint32_t accx[4][4][2] = {};
    float4 av[4], bv[4];

#pragma unroll
    for (int it = 0; it < 4; it++) {
        av[it] = *(const float4*)(x    + (size_t)(m_base + srow[it]) * KDIM + sc4[it] * 4);
        bv[it] = *(const float4*)(w_ih + (size_t)(n_base + srow[it]) * KDIM + sc4[it] * 4);
    }
#pragma unroll
    for (int it = 0; it < 4; it++) {
        split_pair(av[it].x, av[it].y, XA(0, 0, srow[it], sc4[it] * 2), XA(1, 0, srow[it], sc4[it] * 2));
        split_pair(av[it].z, av[it].w, XA(0, 0, srow[it], sc4[it] * 2 + 1), XA(1, 0, srow[it], sc4[it] * 2 + 1));
        split_pair(bv[it].x, bv[it].y, XA(2, 0, srow[it], sc4[it] * 2), XA(3, 0, srow[it], sc4[it] * 2));
        split_pair(bv[it].z, bv[it].w, XA(2, 0, srow[it], sc4[it] * 2 + 1), XA(3, 0, srow[it], sc4[it] * 2 + 1));
    }

#pragma unroll 1
    for (int c = 0; c < 32; c++) {
        if (c < 31) {
            int k0 = (c + 1) * 32;
#pragma unroll
            for (int it = 0; it < 4; it++) {
                av[it] = *(const float4*)(x    + (size_t)(m_base + srow[it]) * KDIM + k0 + sc4[it] * 4);
                bv[it] = *(const float4*)(w_ih + (size_t)(n_base + srow[it]) * KDIM + k0 + sc4[it] * 4);
            }
        }
        __syncthreads();
        if (c < 31) {
            int nb = (c + 1) & 1;
#pragma unroll
            for (int it = 0; it < 4; it++) {
                split_pair(av[it].x, av[it].y, XA(0, nb, srow[it], sc4[it] * 2), XA(1, nb, srow[it], sc4[it] * 2));
                split_pair(av[it].z, av[it].w, XA(0, nb, srow[it], sc4[it] * 2 + 1), XA(1, nb, srow[it], sc4[it] * 2 + 1));
                split_pair(bv[it].x, bv[it].y, XA(2, nb, srow[it], sc4[it] * 2), XA(3, nb, srow[it], sc4[it] * 2));
                split_pair(bv[it].z, bv[it].w, XA(2, nb, srow[it], sc4[it] * 2 + 1), XA(3, nb, srow[it], sc4[it] * 2 + 1));
            }
        }
        int bsel = c & 1;
#pragma unroll
        for (int kk = 0; kk < 2; kk++) {
            uint32_t afh[4][4], afm[4][4];
#pragma unroll
            for (int mi = 0; mi < 4; mi++) {
                int r = wm * 64 + mi * 16;
                afh[mi][0] = XA(0, bsel, r + g, kk * 8 + tg);
                afh[mi][1] = XA(0, bsel, r + g + 8, kk * 8 + tg);
                afh[mi][2] = XA(0, bsel, r + g, kk * 8 + tg + 4);
                afh[mi][3] = XA(0, bsel, r + g + 8, kk * 8 + tg + 4);
                afm[mi][0] = XA(1, bsel, r + g, kk * 8 + tg);
                afm[mi][1] = XA(1, bsel, r + g + 8, kk * 8 + tg);
                afm[mi][2] = XA(1, bsel, r + g, kk * 8 + tg + 4);
                afm[mi][3] = XA(1, bsel, r + g + 8, kk * 8 + tg + 4);
            }
#pragma unroll
            for (int ni = 0; ni < 4; ni++) {
                int rn = wn * 32 + ni * 8 + g;
                uint32_t bfh[2] = {XA(2, bsel, rn, kk * 8 + tg), XA(2, bsel, rn, kk * 8 + tg + 4)};
                uint32_t bfm[2] = {XA(3, bsel, rn, kk * 8 + tg), XA(3, bsel, rn, kk * 8 + tg + 4)};
#pragma unroll
                for (int mi = 0; mi < 4; mi++) {
                    mma16h(accx[mi][ni], afh[mi], bfm);
                    mma16h(accx[mi][ni], afm[mi], bfh);
                    mma16(acc[mi][ni], afh[mi], bfh);
                }
            }
        }
    }

    int bflag = *biasflag;
#pragma unroll
    for (int mi = 0; mi < 4; mi++) {
#pragma unroll
        for (int ni = 0; ni < 4; ni++) {
            merge_cross(acc[mi][ni], accx[mi][ni]);
            int row0 = m_base + wm * 64 + mi * 16 + g;
            int col0 = n_base + wn * 32 + ni * 8 + 2 * tg;
            float bs0 = bflag ? (b_ih[col0] + b_hh[col0]) : 0.0f;
            float bs1 = bflag ? (b_ih[col0 + 1] + b_hh[col0 + 1]) : 0.0f;
            g_Zx[(size_t)row0 * G4 + col0]           = acc[mi][ni][0] + bs0;
            g_Zx[(size_t)row0 * G4 + col0 + 1]       = acc[mi][ni][1] + bs1;
            g_Zx[(size_t)(row0 + 8) * G4 + col0]     = acc[mi][ni][2] + bs0;
            g_Zx[(size_t)(row0 + 8) * G4 + col0 + 1] = acc[mi][ni][3] + bs1;
        }
    }
}

// ============ Phase 2: K-split recurrence, 2 CTAs/SM co-resident ===========
extern __shared__ char rsm[];
#define SA2(buf, hm, row, col) sAu[((((buf) * 2 + (hm)) * 64 + (row)) * ASTR) + (col)]
__global__ void __launch_bounds__(256, 2)
recur_kernel(const float* __restrict__ h0, const float* __restrict__ c0,
             float* __restrict__ out) {
    uint2*    sWfH = (uint2*)rsm;                        // 4096 uint2 = 32KB
    uint2*    sWfM = sWfH + SLOTS2;                      // 32KB
    uint32_t* sAu  = (uint32_t*)(sWfM + SLOTS2);         // [2 buf][2 hm][64][ASTR] = 36KB
    float*    zsm  = (float*)(sAu + 2 * 2 * 64 * ASTR);  // 64*33*4 = 8.25KB

    int tid = threadIdx.x, warp = tid >> 5, lane = tid & 31;
    int g = lane >> 2, tg = lane & 3;
    int wm = warp & 3, wn = warp >> 2;
    int jj_grp = blockIdx.x >> 1;        // hidden-col group 0..127
    int shalf = blockIdx.x & 1;          // K-half
    int j0 = jj_grp * 8;
    int kbase = shalf * 512;

    {
        const uint2* gH = g_WfragH + (size_t)blockIdx.x * SLOTS2;
        const uint2* gM = g_WfragM + (size_t)blockIdx.x * SLOTS2;
        for (int i = tid; i < SLOTS2; i += 256) {
            sWfH[i] = gH[i];
            sWfM[i] = gM[i];
        }
    }

    int b0e = tid >> 3, jj0 = tid & 7;
    int b1e = (tid + 256) >> 3, jj1 = (tid + 256) & 7;
    float creg0 = 0.f, creg1 = 0.f;
    if (!shalf) {
        creg0 = c0[b0e * HDIM + j0 + jj0];
        creg1 = c0[b1e * HDIM + j0 + jj1];
    }
    float buf0[4] = {0.f, 0.f, 0.f, 0.f};
    float buf1[4] = {0.f, 0.f, 0.f, 0.f};
    float hlast0 = 0.f, hlast1 = 0.f;

    int arow[4], ac4[4];
#pragma unroll
    for (int it = 0; it < 4; it++) {
        int i = tid + it * 256;
        arow[it] = i >> 4;
        ac4[it] = i & 15;
    }

    uint32_t sA_base = (uint32_t)__cvta_generic_to_shared(sAu);
    int lrow = wm * 16 + (lane & 7) + ((lane >> 3) & 1) * 8;
    uint32_t lrow_off = (uint32_t)(lrow * ASTR) * 4;
    uint32_t lcol_off = (uint32_t)((lane >> 4) * 4) * 4;
    const uint32_t HM_OFF  = (uint32_t)(64 * ASTR) * 4;
    const uint32_t BUF_OFF = (uint32_t)(2 * 64 * ASTR) * 4;

    float* mypart = g_Part + (size_t)jj_grp * 2048;

    size_t zb0 = (size_t)b0e * G4 + (j0 + jj0);
    size_t zb1 = (size_t)b1e * G4 + (j0 + jj1);
    float zx0[4], zx1[4];
    if (!shalf) {
#pragma unroll
        for (int q = 0; q < 4; q++) {
            zx0[q] = g_Zx[zb0 + (size_t)q * 1024];
            zx1[q] = g_Zx[zb1 + (size_t)q * 1024];
        }
    }
    __syncthreads();   // W fragments visible

    for (int t = 0; t < T_STEPS; t++) {
        const float* hsrc = (t == 0) ? h0 : (out + (size_t)(t - 1) * BATCH * HDIM);

        // Prologue: LDG chunk 0 of this K-half
        float4 va[4];
#pragma unroll
        for (int it = 0; it < 4; it++)
            va[it] = *(const float4*)(hsrc + (size_t)arow[it] * HDIM + kbase + ac4[it] * 4);

        float acc[2][4] = {};
        uint32_t accx[2][2] = {};
#pragma unroll 1
        for (int c = 0; c < 8; c++) {
            int bsel = c & 1;
#pragma unroll
            for (int it = 0; it < 4; it++) {
                split_pair(va[it].x, va[it].y,
                           SA2(bsel, 0, arow[it], ac4[it] * 2),
                           SA2(bsel, 1, arow[it], ac4[it] * 2));
                split_pair(va[it].z, va[it].w,
                           SA2(bsel, 0, arow[it], ac4[it] * 2 + 1),
                           SA2(bsel, 1, arow[it], ac4[it] * 2 + 1));
            }
            __syncthreads();
            if (c < 7) {
                int k0 = kbase + (c + 1) * 64;
#pragma unroll
                for (int it = 0; it < 4; it++)
                    va[it] = *(const float4*)(hsrc + (size_t)arow[it] * HDIM + k0 + ac4[it] * 4);
            }
            uint32_t abase = sA_base + (uint32_t)bsel * BUF_OFF + lrow_off + lcol_off;
#pragma unroll
            for (int kk = 0; kk < 4; kk++) {
                uint32_t afh[4], afm[4];
                uint32_t ka = abase + (uint32_t)(kk * 8) * 4;
                ldsm_x4(afh, ka);
                ldsm_x4(afm, ka + HM_OFF);
#pragma unroll
                for (int nt = 0; nt < 2; nt++) {
                    int fb = (((c * 4 + kk) * 2 + wn) * 2 + nt) * 32 + lane;
                    uint2 bh = sWfH[fb], bm = sWfM[fb];
                    uint32_t bfh[2] = {bh.x, bh.y};
                    uint32_t bfm[2] = {bm.x, bm.y};
                    mma16h(accx[nt], afh, bfm);
                    mma16h(accx[nt], afm, bfh);
                    mma16(acc[nt], afh, bfh);
                }
            }
        }
        merge_cross(acc[0], accx[0]);
        merge_cross(acc[1], accx[1]);

        int r0 = wm * 16 + g;
        if (shalf) {
            // Producer: post partial tile (L2-resident, bypass L1)
#pragma unroll
            for (int nt = 0; nt < 2; nt++) {
                int cw = wn * 16 + nt * 8 + 2 * tg;
                __stcg(mypart + r0 * 32 + cw,           acc[nt][0]);
                __stcg(mypart + r0 * 32 + cw + 1,       acc[nt][1]);
                __stcg(mypart + (r0 + 8) * 32 + cw,     acc[nt][2]);
                __stcg(mypart + (r0 + 8) * 32 + cw + 1, acc[nt][3]);
            }
            __syncthreads();   // all partial stores issued before release
            if (tid == 0)
                asm volatile("st.release.gpu.u32 [%0], %1;"
                             :: "l"(&g_pflags[jj_grp * 32]), "r"((unsigned)(t + 1)) : "memory");
        } else {
            // Consumer: wait for partner's partial, add, then gates
            if (tid == 0) {
                unsigned v;
                do {
                    asm volatile("ld.acquire.gpu.u32 %0, [%1];"
                                 : "=r"(v) : "l"(&g_pflags[jj_grp * 32]) : "memory");
                } while (v < (unsigned)(t + 1));
            }
            __syncthreads();
#pragma unroll
            for (int nt = 0; nt < 2; nt++) {
                int cw = wn * 16 + nt * 8 + 2 * tg;
                acc[nt][0] += __ldcg(mypart + r0 * 32 + cw);
                acc[nt][1] += __ldcg(mypart + r0 * 32 + cw + 1);
                acc[nt][2] += __ldcg(mypart + (r0 + 8) * 32 + cw);
                acc[nt][3] += __ldcg(mypart + (r0 + 8) * 32 + cw + 1);
            }
            // Scatter z tile
#pragma unroll
            for (int nt = 0; nt < 2; nt++) {
                int cc2 = wn * 16 + nt * 8 + 2 * tg;
                zsm[r0 * 33 + cc2]           = acc[nt][0];
                zsm[r0 * 33 + cc2 + 1]       = acc[nt][1];
                zsm[(r0 + 8) * 33 + cc2]     = acc[nt][2];
                zsm[(r0 + 8) * 33 + cc2 + 1] = acc[nt][3];
            }
            __syncthreads();

            {
                float zi = zsm[b0e * 33 + jj0]      + zx0[0];
                float zf = zsm[b0e * 33 + 8 + jj0]  + zx0[1];
                float zg = zsm[b0e * 33 + 16 + jj0] + zx0[2];
                float zo = zsm[b0e * 33 + 24 + jj0] + zx0[3];
                float cn = sigmf(zf) * creg0 + sigmf(zi) * tanhf(zg);
                float h = sigmf(zo) * tanhf(cn);
                int idx = t & 3;
                if (t >= 4) h += buf0[idx];
                buf0[idx] = h;
                creg0 = cn;
                hlast0 = h;
                out[(size_t)t * BATCH * HDIM + b0e * HDIM + j0 + jj0] = h;
            }
            {
                float zi = zsm[b1e * 33 + jj1]      + zx1[0];
                float zf = zsm[b1e * 33 + 8 + jj1]  + zx1[1];
                float zg = zsm[b1e * 33 + 16 + jj1] + zx1[2];
                float zo = zsm[b1e * 33 + 24 + jj1] + zx1[3];
                float cn = sigmf(zf) * creg1 + sigmf(zi) * tanhf(zg);
                float h = sigmf(zo) * tanhf(cn);
                int idx = t & 3;
                if (t >= 4) h += buf1[idx];
                buf1[idx] = h;
                creg1 = cn;
                hlast1 = h;
                out[(size_t)t * BATCH * HDIM + b1e * HDIM + j0 + jj1] = h;
            }

            // Prefetch next step's Zx before the barrier
            if (t + 1 < T_STEPS) {
                size_t zn = (size_t)(t + 1) * BATCH * G4;
#pragma unroll
                for (int q = 0; q < 4; q++) {
                    zx0[q] = g_Zx[zn + zb0 + (size_t)q * 1024];
                    zx1[q] = g_Zx[zn + zb1 + (size_t)q * 1024];
                }
            }
        }

        // Global step barrier across all 256 CTAs
        __syncthreads();
        if (tid == 0)
            asm volatile("st.release.gpu.u32 [%0], %1;"
                         :: "l"(&g_flags[blockIdx.x * 32]), "r"((unsigned)(t + 1)) : "memory");
        {   // all 256 threads poll one flag each
            unsigned v;
            do {
                asm volatile("ld.acquire.gpu.u32 %0, [%1];"
                             : "=r"(v) : "l"(&g_flags[tid * 32]) : "memory");
            } while (v < (unsigned)(t + 1));
        }
        __syncthreads();
    }

    if (!shalf) {
        float* hfin = out + (size_t)T_STEPS * BATCH * HDIM;
        float* cfin = hfin + BATCH * HDIM;
        hfin[b0e * HDIM + j0 + jj0] = hlast0;
        hfin[b1e * HDIM + j0 + jj1] = hlast1;
        cfin[b0e * HDIM + j0 + jj0] = creg0;
        cfin[b1e * HDIM + j0 + jj1] = creg1;
    }
}

extern "C" void kernel_launch(void* const* d_in, const int* in_sizes, int n_in,
                              void* d_out, int out_size) {
    const float* x    = (const float*)d_in[0];
    const float* h0   = (const float*)d_in[1];
    const float* c0   = (const float*)d_in[2];
    const float* w_ih = (const float*)d_in[3];
    const float* w_hh = (const float*)d_in[4];
    const float* b_ih = (const float*)d_in[5];
    const float* b_hh = (const float*)d_in[6];
    const int* bias   = (const int*)d_in[7];
    float* out = (float*)d_out;

    const int XSMEM = 4 * 2 * 128 * XSTR * 4;                               // 81920
    const int RSMEM = SLOTS2 * 8 * 2 + 2 * 2 * 64 * ASTR * 4 + 64 * 33 * 4; // 110848
    cudaFuncSetAttribute(xproj_kernel, cudaFuncAttributeMaxDynamicSharedMemorySize, XSMEM);
    cudaFuncSetAttribute(recur_kernel, cudaFuncAttributeMaxDynamicSharedMemorySize, RSMEM);

    wfrag_kernel<<<(NCTA2 * SLOTS2) / 256, 256>>>(w_hh);
    dim3 g1(G4 / 128, (T_STEPS * BATCH) / 128);  // (32, 256)
    xproj_kernel<<<g1, 256, XSMEM>>>(x, w_ih, b_ih, b_hh, bias);
    recur_kernel<<<NCTA2, 256, RSMEM>>>(h0, c0, out);
}

// round 17
// speedup vs baseline: 1.1491x; 1.1491x over previous
#include <cuda_runtime.h>
#include <cuda_fp16.h>
#include <cstdint>

#define T_STEPS 512
#define BATCH   64
#define IDIM    1024
#define HDIM    1024
#define G4      4096
#define KDIM    1024
#define NCTA    128
#define SLOTS   8192            // uint2 fragment slots per CTA per array
#define ASTR    36              // recur A smem row stride (conflict-free for LDSM)
#define XSTR    20              // xproj smem row stride (16 pairs + 4 pad)

__device__ float g_Zx[(size_t)T_STEPS * BATCH * G4];
__device__ uint2 g_WfragH[(size_t)NCTA * SLOTS];
__device__ uint2 g_WfragM[(size_t)NCTA * SLOTS];
__device__ unsigned g_flags[NCTA * 32];   // distributed barrier flags, 128B apart

// ---------------------------------------------------------------- helpers
__device__ __forceinline__ void split_pair(float e, float o, uint32_t& ph, uint32_t& pm) {
    __half2 hp = __floats2half2_rn(e, o);
    float2 hf = __half22float2(hp);
    __half2 mp = __floats2half2_rn(e - hf.x, o - hf.y);
    ph = *reinterpret_cast<uint32_t*>(&hp);
    pm = *reinterpret_cast<uint32_t*>(&mp);
}
__device__ __forceinline__ void mma16(float* c, const uint32_t* a, const uint32_t* b) {
    asm volatile(
        "mma.sync.aligned.m16n8k16.row.col.f32.f16.f16.f32 "
        "{%0,%1,%2,%3},{%4,%5,%6,%7},{%8,%9},{%0,%1,%2,%3};\n"
        : "+f"(c[0]), "+f"(c[1]), "+f"(c[2]), "+f"(c[3])
        : "r"(a[0]), "r"(a[1]), "r"(a[2]), "r"(a[3]), "r"(b[0]), "r"(b[1]));
}
__device__ __forceinline__ void mma16h(uint32_t* c, const uint32_t* a, const uint32_t* b) {
    asm volatile(
        "mma.sync.aligned.m16n8k16.row.col.f16.f16.f16.f16 "
        "{%0,%1},{%2,%3,%4,%5},{%6,%7},{%0,%1};\n"
        : "+r"(c[0]), "+r"(c[1])
        : "r"(a[0]), "r"(a[1]), "r"(a[2]), "r"(a[3]), "r"(b[0]), "r"(b[1]));
}
__device__ __forceinline__ void ldsm_x4(uint32_t* r, uint32_t saddr) {
    asm volatile("ldmatrix.sync.aligned.m8n8.x4.shared.b16 {%0,%1,%2,%3}, [%4];"
                 : "=r"(r[0]), "=r"(r[1]), "=r"(r[2]), "=r"(r[3]) : "r"(saddr));
}
__device__ __forceinline__ void merge_cross(float* acc, const uint32_t* cx) {
    float2 lo = __half22float2(*reinterpret_cast<const __half2*>(&cx[0]));
    float2 hi = __half22float2(*reinterpret_cast<const __half2*>(&cx[1]));
    acc[0] += lo.x; acc[1] += lo.y; acc[2] += hi.x; acc[3] += hi.y;
}
// Fast gate math (range-safe). sigmoid: exp(-x) may overflow to inf -> rcp
// gives 0 (correct limit). tanh: use |x| so the exponential is always <= 1,
// underflow -> t = 1 (correct limit); sign restored with copysignf.
__device__ __forceinline__ float sigmf(float x) {
    return __fdividef(1.0f, 1.0f + __expf(-x));
}
__device__ __forceinline__ float tanhf_fast(float x) {
    float e = __expf(-2.0f * fabsf(x));            // in (0, 1], never overflows
    float t = __fdividef(1.0f - e, 1.0f + e);
    return copysignf(t, x);
}

// ====== wfrag: permute w_hh into per-CTA MMA-fragment order; reset flags ===
__global__ void __launch_bounds__(256)
wfrag_kernel(const float* __restrict__ w_hh) {
    size_t s = (size_t)blockIdx.x * 256 + threadIdx.x;
    if (s < NCTA) g_flags[s * 32] = 0u;
    int cta = (int)(s >> 13);
    int r = (int)(s & (SLOTS - 1));
    int lane = r & 31, q = r >> 5;
    int nt = q & 1, wn = (q >> 1) & 1, kk = (q >> 2) & 3, c = q >> 4;
    int g = lane >> 2, tg = lane & 3;
    int row = wn * 16 + nt * 8 + g;
    size_t R = (size_t)((row >> 3) * HDIM + cta * 8 + (row & 7));
    int p0 = c * 32 + kk * 8 + tg;
    const float* wr = w_hh + R * KDIM;
    uint32_t h0w, m0w, h1w, m1w;
    split_pair(wr[2 * p0],     wr[2 * p0 + 1], h0w, m0w);
    split_pair(wr[2 * p0 + 8], wr[2 * p0 + 9], h1w, m1w);
    g_WfragH[s] = make_uint2(h0w, h1w);
    g_WfragM[s] = make_uint2(m0w, m1w);
}

// ============ Phase 1: Z_x = x @ w_ih^T + bias (R10-exact) =================
extern __shared__ uint32_t xsm_u[];
#define XA(arr, buf, row, col) xsm_u[((((arr) * 2 + (buf)) * 128 + (row)) * XSTR) + (col)]
__global__ void __launch_bounds__(256)
xproj_kernel(const float* __restrict__ x, const float* __restrict__ w_ih,
             const float* __restrict__ b_ih, const float* __restrict__ b_hh,
             const int* __restrict__ biasflag) {
    int tid = threadIdx.x, warp = tid >> 5, lane = tid & 31;
    int g = lane >> 2, tg = lane & 3;
    int wm = warp >> 2, wn = warp & 3;
    int m_base = blockIdx.y * 128, n_base = blockIdx.x * 128;

    int srow[4], sc4[4];
#pragma unroll
    for (int it = 0; it < 4; it++) {
        int i = tid + it * 256;
        srow[it] = i >> 3;
        sc4[it] = i & 7;
    }

    float acc[4][4][4] = {};
    uint32_t accx[4][4][2] = {};
    float4 av[4], bv[4];

#pragma unroll
    for (int it = 0; it < 4; it++) {
        av[it] = *(const float4*)(x    + (size_t)(m_base + srow[it]) * KDIM + sc4[it] * 4);
        bv[it] = *(const float4*)(w_ih + (size_t)(n_base + srow[it]) * KDIM + sc4[it] * 4);
    }
#pragma unroll
    for (int it = 0; it < 4; it++) {
        split_pair(av[it].x, av[it].y, XA(0, 0, srow[it], sc4[it] * 2), XA(1, 0, srow[it], sc4[it] * 2));
        split_pair(av[it].z, av[it].w, XA(0, 0, srow[it], sc4[it] * 2 + 1), XA(1, 0, srow[it], sc4[it] * 2 + 1));
        split_pair(bv[it].x, bv[it].y, XA(2, 0, srow[it], sc4[it] * 2), XA(3, 0, srow[it], sc4[it] * 2));
        split_pair(bv[it].z, bv[it].w, XA(2, 0, srow[it], sc4[it] * 2 + 1), XA(3, 0, srow[it], sc4[it] * 2 + 1));
    }

#pragma unroll 1
    for (int c = 0; c < 32; c++) {
        if (c < 31) {
            int k0 = (c + 1) * 32;
#pragma unroll
            for (int it = 0; it < 4; it++) {
                av[it] = *(const float4*)(x    + (size_t)(m_base + srow[it]) * KDIM + k0 + sc4[it] * 4);
                bv[it] = *(const float4*)(w_ih + (size_t)(n_base + srow[it]) * KDIM + k0 + sc4[it] * 4);
            }
        }
        __syncthreads();
        if (c < 31) {
            int nb = (c + 1) & 1;
#pragma unroll
            for (int it = 0; it < 4; it++) {
                split_pair(av[it].x, av[it].y, XA(0, nb, srow[it], sc4[it] * 2), XA(1, nb, srow[it], sc4[it] * 2));
                split_pair(av[it].z, av[it].w, XA(0, nb, srow[it], sc4[it] * 2 + 1), XA(1, nb, srow[it], sc4[it] * 2 + 1));
                split_pair(bv[it].x, bv[it].y, XA(2, nb, srow[it], sc4[it] * 2), XA(3, nb, srow[it], sc4[it] * 2));
                split_pair(bv[it].z, bv[it].w, XA(2, nb, srow[it], sc4[it] * 2 + 1), XA(3, nb, srow[it], sc4[it] * 2 + 1));
            }
        }
        int bsel = c & 1;
#pragma unroll
        for (int kk = 0; kk < 2; kk++) {
            uint32_t afh[4][4], afm[4][4];
#pragma unroll
            for (int mi = 0; mi < 4; mi++) {
                int r = wm * 64 + mi * 16;
                afh[mi][0] = XA(0, bsel, r + g, kk * 8 + tg);
                afh[mi][1] = XA(0, bsel, r + g + 8, kk * 8 + tg);
                afh[mi][2] = XA(0, bsel, r + g, kk * 8 + tg + 4);
                afh[mi][3] = XA(0, bsel, r + g + 8, kk * 8 + tg + 4);
                afm[mi][0] = XA(1, bsel, r + g, kk * 8 + tg);
                afm[mi][1] = XA(1, bsel, r + g + 8, kk * 8 + tg);
                afm[mi][2] = XA(1, bsel, r + g, kk * 8 + tg + 4);
                afm[mi][3] = XA(1, bsel, r + g + 8, kk * 8 + tg + 4);
            }
#pragma unroll
            for (int ni = 0; ni < 4; ni++) {
                int rn = wn * 32 + ni * 8 + g;
                uint32_t bfh[2] = {XA(2, bsel, rn, kk * 8 + tg), XA(2, bsel, rn, kk * 8 + tg + 4)};
                uint32_t bfm[2] = {XA(3, bsel, rn, kk * 8 + tg), XA(3, bsel, rn, kk * 8 + tg + 4)};
#pragma unroll
                for (int mi = 0; mi < 4; mi++) {
                    mma16h(accx[mi][ni], afh[mi], bfm);
                    mma16h(accx[mi][ni], afm[mi], bfh);
                    mma16(acc[mi][ni], afh[mi], bfh);
                }
            }
        }
    }

    int bflag = *biasflag;
#pragma unroll
    for (int mi = 0; mi < 4; mi++) {
#pragma unroll
        for (int ni = 0; ni < 4; ni++) {
            merge_cross(acc[mi][ni], accx[mi][ni]);
            int row0 = m_base + wm * 64 + mi * 16 + g;
            int col0 = n_base + wn * 32 + ni * 8 + 2 * tg;
            float bs0 = bflag ? (b_ih[col0] + b_hh[col0]) : 0.0f;
            float bs1 = bflag ? (b_ih[col0 + 1] + b_hh[col0 + 1]) : 0.0f;
            g_Zx[(size_t)row0 * G4 + col0]           = acc[mi][ni][0] + bs0;
            g_Zx[(size_t)row0 * G4 + col0 + 1]       = acc[mi][ni][1] + bs1;
            g_Zx[(size_t)(row0 + 8) * G4 + col0]     = acc[mi][ni][2] + bs0;
            g_Zx[(size_t)(row0 + 8) * G4 + col0 + 1] = acc[mi][ni][3] + bs1;
        }
    }
}

// ============ Phase 2: recurrence (R14 + range-safe fast gate math) ========
extern __shared__ char rsm[];
#define SA4(buf, hm, row, col) sAu[((((buf) * 2 + (hm)) * 64 + (row)) * ASTR) + (col)]
__global__ void __launch_bounds__(256, 1)
recur_kernel(const float* __restrict__ h0, const float* __restrict__ c0,
             float* __restrict__ out) {
    uint2*    sWfH = (uint2*)rsm;
    uint2*    sWfM = sWfH + SLOTS;
    uint32_t* sAu  = (uint32_t*)(sWfM + SLOTS);          // [4 buf][2 hm][64][ASTR]
    float*    zsm  = (float*)(sAu + 4 * 2 * 64 * ASTR);

    int tid = threadIdx.x, warp = tid >> 5, lane = tid & 31;
    int g = lane >> 2, tg = lane & 3;
    int wm = warp & 3, wn = warp >> 2;
    int j0 = blockIdx.x * 8;

    {
        const uint2* gH = g_WfragH + (size_t)blockIdx.x * SLOTS;
        const uint2* gM = g_WfragM + (size_t)blockIdx.x * SLOTS;
        for (int i = tid; i < SLOTS; i += 256) {
            sWfH[i] = gH[i];
            sWfM[i] = gM[i];
        }
    }

    int b0e = tid >> 3, jj0 = tid & 7;
    int b1e = (tid + 256) >> 3, jj1 = (tid + 256) & 7;
    float creg0 = c0[b0e * HDIM + j0 + jj0];
    float creg1 = c0[b1e * HDIM + j0 + jj1];
    float buf0[4] = {0.f, 0.f, 0.f, 0.f};
    float buf1[4] = {0.f, 0.f, 0.f, 0.f};
    float hlast0 = 0.f, hlast1 = 0.f;

    int arow[4], ac4[4];
#pragma unroll
    for (int it = 0; it < 4; it++) {
        int i = tid + it * 256;
        arow[it] = i >> 4;
        ac4[it] = i & 15;
    }

    uint32_t sA_base = (uint32_t)__cvta_generic_to_shared(sAu);
    int lrow = wm * 16 + (lane & 7) + ((lane >> 3) & 1) * 8;
    uint32_t lrow_off = (uint32_t)(lrow * ASTR) * 4;
    uint32_t lcol_off = (uint32_t)((lane >> 4) * 4) * 4;
    const uint32_t HM_OFF  = (uint32_t)(64 * ASTR) * 4;
    const uint32_t BUF_OFF = (uint32_t)(2 * 64 * ASTR) * 4;

    size_t zb0 = (size_t)b0e * G4 + (j0 + jj0);
    size_t zb1 = (size_t)b1e * G4 + (j0 + jj1);
    float zx0[4], zx1[4];
#pragma unroll
    for (int q = 0; q < 4; q++) {
        zx0[q] = g_Zx[zb0 + (size_t)q * 1024];
        zx1[q] = g_Zx[zb1 + (size_t)q * 1024];
    }
    __syncthreads();   // W fragments visible

    for (int t = 0; t < T_STEPS; t++) {
        const float* hsrc = (t == 0) ? h0 : (out + (size_t)(t - 1) * BATCH * HDIM);

        // Prologue: LDG chunks 0,1
        float4 va[2][4];
#pragma unroll
        for (int half = 0; half < 2; half++)
#pragma unroll
            for (int it = 0; it < 4; it++)
                va[half][it] = *(const float4*)(hsrc + (size_t)arow[it] * HDIM +
                                                half * 64 + ac4[it] * 4);

        float acc[2][4] = {};
        uint32_t accx[2][2] = {};
#pragma unroll 1
        for (int cc = 0; cc < 8; cc++) {
            // split chunks 2cc, 2cc+1 (split -> sync -> LDG -> MMA)
#pragma unroll
            for (int half = 0; half < 2; half++) {
                int bsel = (2 * cc + half) & 3;
#pragma unroll
                for (int it = 0; it < 4; it++) {
                    split_pair(va[half][it].x, va[half][it].y,
                               SA4(bsel, 0, arow[it], ac4[it] * 2),
                               SA4(bsel, 1, arow[it], ac4[it] * 2));
                    split_pair(va[half][it].z, va[half][it].w,
                               SA4(bsel, 0, arow[it], ac4[it] * 2 + 1),
                               SA4(bsel, 1, arow[it], ac4[it] * 2 + 1));
                }
            }
            __syncthreads();
            if (cc < 7) {
#pragma unroll
                for (int half = 0; half < 2; half++) {
                    int k0 = (2 * cc + 2 + half) * 64;
#pragma unroll
                    for (int it = 0; it < 4; it++)
                        va[half][it] = *(const float4*)(hsrc + (size_t)arow[it] * HDIM +
                                                        k0 + ac4[it] * 4);
                }
            }
#pragma unroll
            for (int half = 0; half < 2; half++) {
                int c = 2 * cc + half, bsel = c & 3;
                uint32_t abase = sA_base + (uint32_t)bsel * BUF_OFF + lrow_off + lcol_off;
#pragma unroll
                for (int kk = 0; kk < 4; kk++) {
                    uint32_t afh[4], afm[4];
                    uint32_t ka = abase + (uint32_t)(kk * 8) * 4;
                    ldsm_x4(afh, ka);
                    ldsm_x4(afm, ka + HM_OFF);
#pragma unroll
                    for (int nt = 0; nt < 2; nt++) {
                        int fb = (((c * 4 + kk) * 2 + wn) * 2 + nt) * 32 + lane;
                        uint2 bh = sWfH[fb], bm = sWfM[fb];
                        uint32_t bfh[2] = {bh.x, bh.y};
                        uint32_t bfm[2] = {bm.x, bm.y};
                        mma16h(accx[nt], afh, bfm);
                        mma16h(accx[nt], afm, bfh);
                        mma16(acc[nt], afh, bfh);
                    }
                }
            }
        }
        merge_cross(acc[0], accx[0]);
        merge_cross(acc[1], accx[1]);

        // Scatter z tile (zsm disjoint from sA)
        {
            int r0 = wm * 16 + g;
#pragma unroll
            for (int nt = 0; nt < 2; nt++) {
                int cc2 = wn * 16 + nt * 8 + 2 * tg;
                zsm[r0 * 33 + cc2]           = acc[nt][0];
                zsm[r0 * 33 + cc2 + 1]       = acc[nt][1];
                zsm[(r0 + 8) * 33 + cc2]     = acc[nt][2];
                zsm[(r0 + 8) * 33 + cc2 + 1] = acc[nt][3];
            }
        }
        __syncthreads();

        {
            float zi = zsm[b0e * 33 + jj0]      + zx0[0];
            float zf = zsm[b0e * 33 + 8 + jj0]  + zx0[1];
            float zg = zsm[b0e * 33 + 16 + jj0] + zx0[2];
            float zo = zsm[b0e * 33 + 24 + jj0] + zx0[3];
            float cn = sigmf(zf) * creg0 + sigmf(zi) * tanhf_fast(zg);
            float h = sigmf(zo) * tanhf_fast(cn);
            int idx = t & 3;
            if (t >= 4) h += buf0[idx];
            buf0[idx] = h;
            creg0 = cn;
            hlast0 = h;
            out[(size_t)t * BATCH * HDIM + b0e * HDIM + j0 + jj0] = h;
        }
        {
            float zi = zsm[b1e * 33 + jj1]      + zx1[0];
            float zf = zsm[b1e * 33 + 8 + jj1]  + zx1[1];
            float zg = zsm[b1e * 33 + 16 + jj1] + zx1[2];
            float zo = zsm[b1e * 33 + 24 + jj1] + zx1[3];
            float cn = sigmf(zf) * creg1 + sigmf(zi) * tanhf_fast(zg);
            float h = sigmf(zo) * tanhf_fast(cn);
            int idx = t & 3;
            if (t >= 4) h += buf1[idx];
            buf1[idx] = h;
            creg1 = cn;
            hlast1 = h;
            out[(size_t)t * BATCH * HDIM + b1e * HDIM + j0 + jj1] = h;
        }

        if (t + 1 < T_STEPS) {
            size_t zn = (size_t)(t + 1) * BATCH * G4;
#pragma unroll
            for (int q = 0; q < 4; q++) {
                zx0[q] = g_Zx[zn + zb0 + (size_t)q * 1024];
                zx1[q] = g_Zx[zn + zb1 + (size_t)q * 1024];
            }
        }

        // Distributed grid barrier: per-CTA release flag + 128-thread poll
        __syncthreads();
        if (tid == 0)
            asm volatile("st.release.gpu.u32 [%0], %1;"
                         :: "l"(&g_flags[blockIdx.x * 32]), "r"((unsigned)(t + 1)) : "memory");
        if (tid < NCTA) {
            unsigned v;
            do {
                asm volatile("ld.acquire.gpu.u32 %0, [%1];"
                             : "=r"(v) : "l"(&g_flags[tid * 32]) : "memory");
            } while (v < (unsigned)(t + 1));
        }
        __syncthreads();
    }

    float* hfin = out + (size_t)T_STEPS * BATCH * HDIM;
    float* cfin = hfin + BATCH * HDIM;
    hfin[b0e * HDIM + j0 + jj0] = hlast0;
    hfin[b1e * HDIM + j0 + jj1] = hlast1;
    cfin[b0e * HDIM + j0 + jj0] = creg0;
    cfin[b1e * HDIM + j0 + jj1] = creg1;
}

extern "C" void kernel_launch(void* const* d_in, const int* in_sizes, int n_in,
                              void* d_out, int out_size) {
    const float* x    = (const float*)d_in[0];
    const float* h0   = (const float*)d_in[1];
    const float* c0   = (const float*)d_in[2];
    const float* w_ih = (const float*)d_in[3];
    const float* w_hh = (const float*)d_in[4];
    const float* b_ih = (const float*)d_in[5];
    const float* b_hh = (const float*)d_in[6];
    const int* bias   = (const int*)d_in[7];
    float* out = (float*)d_out;

    const int XSMEM = 4 * 2 * 128 * XSTR * 4;                              // 81920
    const int RSMEM = SLOTS * 8 * 2 + 4 * 2 * 64 * ASTR * 4 + 64 * 33 * 4; // 213248
    cudaFuncSetAttribute(xproj_kernel, cudaFuncAttributeMaxDynamicSharedMemorySize, XSMEM);
    cudaFuncSetAttribute(recur_kernel, cudaFuncAttributeMaxDynamicSharedMemorySize, RSMEM);

    wfrag_kernel<<<(NCTA * SLOTS) / 256, 256>>>(w_hh);
    dim3 g1(G4 / 128, (T_STEPS * BATCH) / 128);  // (32, 256)
    xproj_kernel<<<g1, 256, XSMEM>>>(x, w_ih, b_ih, b_hh, bias);
    recur_kernel<<<NCTA, 256, RSMEM>>>(h0, c0, out);
}